// round 8
// baseline (speedup 1.0000x reference)
#include <cuda_runtime.h>
#include <math.h>

#define BB 32
#define PP 64
#define LL 64
#define VV 32000
#define NBLK 1184            // 148 SMs * 8 blocks: exact residency fill
#define NROW (BB * PP)       // 2048

// Scratch (no allocations allowed). Zero-initialized at module load.
// g_flag / g_done are reset by the last block each run (graph-replay safe).
__device__ uint2    g_mask[NROW];    // truth bitmask per (b,i)
__device__ int      g_flag[BB];      // DP-done flag per batch
__device__ float    g_sum[NROW];     // per-row sum over V
__device__ float    g_S[NROW];       // per-row sum at distinct argmins
__device__ int      g_m[NROW];       // per-row distinct argmin count
__device__ unsigned g_done;          // block completion counter

// ---------------------------------------------------------------------------
// Single kernel, grid = 1184 x 256: every SM holds exactly 8 resident blocks.
// Block q owns row q, plus row q+1184 when q < 864 (total 2048 rows).
// Order: (DP for blocks 0..31) -> stream owned rows (interleaved when 2,
// unroll-4 when 1; flag-wait only AFTER streaming so DP hides completely)
// -> per-row epilogue (dedup gather, plain stores) -> last-block finisher.
//
// Analytic collapse: q has 2 levels -> p1=e/D, p0=1/D, D=(V-m)+m*e.
// lnD = ln(V) + log1p(m*(e-1)/V);  ln p1 = 1-lnD;  ln p0 = -lnD.
// kl = m*p1*(1-lnD) - (V-m)*p0*lnD - p0*sumAll - (p1-p0)*Ssum
// ---------------------------------------------------------------------------
__global__ void __launch_bounds__(256, 8)
k_main(const float* __restrict__ outputs,
       const int* __restrict__ syms,
       const int* __restrict__ targets,
       const unsigned char* __restrict__ mask,
       float* __restrict__ out) {
    const unsigned FULL = 0xffffffffu;
    int q    = blockIdx.x;            // 0..1183
    int tid  = threadIdx.x;
    int lane = tid & 31, wid = tid >> 5;

    int rowA = q;
    int rowB = q + NBLK;              // valid iff q < NROW - NBLK (864)
    bool twoRows = (rowB < NROW);

    // ---------------- DP (blocks 0..31, warp 0 only) ----------------
    if (q < BB && wid == 0) {
        int bd = q;
        int j0 = 2 * lane, j1 = 2 * lane + 1;
        int tg0 = targets[bd * LL + j0];
        int tg1 = targets[bd * LL + j1];
        int mk0 = mask[bd * LL + j0];
        int mk1 = mask[bd * LL + j1];
        int s0  = syms[bd * PP + j0];
        int s1  = syms[bd * PP + j1];
        int tgm1 = __shfl_up_sync(FULL, tg1, 1);   // tg[j0-1]
        float p0 = (float)j0, p1 = (float)j1;      // row 0 (exact ints in fp32)

        for (int i = 0; i < PP; i++) {
            float d0, d1;
            if (i == 0) {
                d0 = p0; d1 = p1;
            } else {
                int im1 = i - 1;
                int sym = __shfl_sync(FULL, (im1 & 1) ? s1 : s0, im1 >> 1);
                float p1m = __shfl_up_sync(FULL, p1, 1);    // prev[j0-1]
                float tmp0 = (lane == 0) ? (float)i
                           : fminf(p1m + ((sym != tgm1) ? 1.0f : 0.0f), p0 + 1.0f);
                float tmp1 = fminf(p0 + ((sym != tg0) ? 1.0f : 0.0f), p1 + 1.0f);
                float v0 = tmp0 - (float)j0;
                float sB = fminf(v0, tmp1 - (float)j1);     // pair-inclusive
                float sc = sB;
                #pragma unroll
                for (int off = 1; off < 32; off <<= 1) {
                    float o = __shfl_up_sync(FULL, sc, off);
                    if (lane >= off) sc = fminf(sc, o);
                }
                float e = __shfl_up_sync(FULL, sc, 1);      // exclusive prefix
                if (lane == 0) e = INFINITY;
                d0 = (float)j0 + fminf(e, v0);
                d1 = (float)j1 + fminf(e, sB);
                p0 = d0; p1 = d1;
            }
            float md0 = mk0 ? d0 : INFINITY;
            float md1 = mk1 ? d1 : INFINITY;
            float mv = fminf(md0, md1);
            #pragma unroll
            for (int off = 16; off; off >>= 1)
                mv = fminf(mv, __shfl_xor_sync(FULL, mv, off));
            unsigned mE = __ballot_sync(FULL, md0 == mv);
            unsigned mO = __ballot_sync(FULL, md1 == mv);
            if (lane == 0) g_mask[bd * PP + i] = make_uint2(mE, mO);
        }
        __threadfence();
        if (lane == 0) atomicExch(&g_flag[bd], 1);
    }

    // -------- stream owned rows (HBM-bound, fp32) --------------------
    float acc0 = 0.0f, acc1 = 0.0f;
    if (twoRows) {
        const float4* r0 = (const float4*)(outputs + (size_t)rowA * VV);
        const float4* r1 = (const float4*)(outputs + (size_t)rowB * VV);
        int idx = tid;
        #pragma unroll 2
        for (int k = 0; k < 31; k++, idx += 256) {          // 31*256 = 7936
            float4 a = r0[idx];
            float4 c = r1[idx];
            acc0 += (a.x + a.y) + (a.z + a.w);
            acc1 += (c.x + c.y) + (c.z + c.w);
        }
        if (tid < (VV / 4 - 7936)) {                        // tail: 64 float4
            float4 a = r0[7936 + tid];
            float4 c = r1[7936 + tid];
            acc0 += (a.x + a.y) + (a.z + a.w);
            acc1 += (c.x + c.y) + (c.z + c.w);
        }
    } else {
        const float4* r0 = (const float4*)(outputs + (size_t)rowA * VV);
        int idx = tid;
        #pragma unroll 4
        for (int k = 0; k < 31; k++, idx += 256) {
            float4 a = r0[idx];
            acc0 += (a.x + a.y) + (a.z + a.w);
        }
        if (tid < (VV / 4 - 7936)) {
            float4 a = r0[7936 + tid];
            acc0 += (a.x + a.y) + (a.z + a.w);
        }
    }
    #pragma unroll
    for (int off = 16; off; off >>= 1) {
        acc0 += __shfl_down_sync(FULL, acc0, off);
        acc1 += __shfl_down_sync(FULL, acc1, off);
    }
    __shared__ float sred0[8], sred1[8];
    if (lane == 0) { sred0[wid] = acc0; sred1[wid] = acc1; }

    // -------- wait for DP flags of the owned rows' batches -----------
    if (tid == 0) {
        int bA = rowA >> 6;
        while (atomicAdd(&g_flag[bA], 0) == 0) __nanosleep(64);
        if (twoRows) {
            int bB = rowB >> 6;
            while (atomicAdd(&g_flag[bB], 0) == 0) __nanosleep(64);
        }
    }
    __syncthreads();
    __threadfence();

    // -------- per-row epilogue: dedup gather + plain stores ----------
    __shared__ int stg[LL];
    __shared__ unsigned char str[LL];
    __shared__ float sS[2], sm[2];
    int nrows = twoRows ? 2 : 1;
    for (int r = 0; r < nrows; r++) {
        int row = r ? rowB : rowA;
        int b   = row >> 6;
        if (tid < LL) {
            stg[tid] = targets[b * LL + tid];
            uint2 m = g_mask[row];
            str[tid] = (unsigned char)((((tid & 1) ? m.y : m.x) >> (tid >> 1)) & 1);
        }
        __syncthreads();

        float c0 = 0.0f, n0 = 0.0f;
        if (tid < LL && str[tid]) {
            int tv = stg[tid];
            bool first = true;
            for (int k = 0; k < tid; k++)
                if (str[k] && stg[k] == tv) { first = false; break; }
            if (first) { c0 = outputs[(size_t)row * VV + tv]; n0 = 1.0f; }  // L2-hot
        }
        #pragma unroll
        for (int off = 16; off; off >>= 1) {
            c0 += __shfl_down_sync(FULL, c0, off);
            n0 += __shfl_down_sync(FULL, n0, off);
        }
        if (tid < LL && lane == 0) { sS[wid] = c0; sm[wid] = n0; }
        __syncthreads();

        if (tid == 0) {
            const float* sr = r ? sred1 : sred0;
            float s = 0.0f;
            #pragma unroll
            for (int w = 0; w < 8; w++) s += sr[w];
            g_sum[row] = s;
            g_S[row]   = sS[0] + sm[0] * 0.0f + sS[1];   // sS[0]+sS[1]
            g_m[row]   = (int)(sm[0] + sm[1]);
        }
        __syncthreads();
    }

    // ---------------- last-block finisher (all fp32) ----------------
    __shared__ int s_last;
    if (tid == 0) {
        __threadfence();
        unsigned prev = atomicAdd(&g_done, 1u);
        s_last = (prev == (unsigned)(gridDim.x - 1));
    }
    __syncthreads();
    if (!s_last) return;

    // thread t = bb*8 + s : batch bb, rows i = s + 8*k (k<8). Deterministic.
    const float E1f  = 2.71828182845904523f;
    const float EM1V = 1.71828182845904523f / 32000.0f;
    const float LNV  = 10.37349118f;                 // ln(32000)
    int bb = tid >> 3, sl = tid & 7;

    float kacc = 0.0f, cnt = 0.0f;
    #pragma unroll
    for (int k = 0; k < 8; k++) {
        int i  = sl + 8 * k;
        int bp = bb * PP + i;
        if (mask[bb * LL + i]) {
            float mm  = (float)g_m[bp];
            float D   = ((float)VV - mm) + mm * E1f;
            float p0  = 1.0f / D;
            float p1  = E1f * p0;
            float x   = mm * EM1V;
            float l1p = x * (1.0f + x * (-0.5f + x * (0.33333333f + x * -0.25f)));
            float lnD = LNV + l1p;
            kacc += mm * p1 * (1.0f - lnD) - ((float)VV - mm) * p0 * lnD
                  - p0 * g_sum[bp] - (p1 - p0) * g_S[bp];
            cnt  += 1.0f;
        }
    }
    __shared__ float spart[256], scnt[256];
    spart[tid] = kacc; scnt[tid] = cnt;
    __syncthreads();

    if (tid < BB) {
        float s = 0.0f, w = 0.0f;
        #pragma unroll
        for (int k = 0; k < 8; k++) { s += spart[tid * 8 + k]; w += scnt[tid * 8 + k]; }
        float pb = s / (w + 1e-13f);
        float ne = (w > 0.0f) ? 1.0f : 0.0f;
        #pragma unroll
        for (int off = 16; off; off >>= 1) {
            pb += __shfl_down_sync(FULL, pb, off);
            ne += __shfl_down_sync(FULL, ne, off);
        }
        if (tid == 0) out[0] = pb / (ne + 1e-13f);
        g_flag[tid] = 0;                   // reset handshake for next replay
        if (tid == 0) g_done = 0u;
    }
}

// ---------------------------------------------------------------------------
extern "C" void kernel_launch(void* const* d_in, const int* in_sizes, int n_in,
                              void* d_out, int out_size) {
    const float*         outputs = (const float*)d_in[0];
    const int*           syms    = (const int*)d_in[1];
    const int*           targets = (const int*)d_in[2];
    const unsigned char* mask    = (const unsigned char*)d_in[3];

    k_main<<<NBLK, 256>>>(outputs, syms, targets, mask, (float*)d_out);
}